// round 6
// baseline (speedup 1.0000x reference)
#include <cuda_runtime.h>
#include <cuda_bf16.h>

#define B_DIM 32
#define T_DIM 1024
#define J_DIM 52
#define NBT (B_DIM * T_DIM)

// Convert one rot6d (6 floats) to a 3x3 rotation matrix, row-major,
// columns = (b1, b2, b3).
__device__ __forceinline__ void rot6d_to_mat(const float* __restrict__ v, float L[9]) {
    float a1x = v[0], a1y = v[1], a1z = v[2];
    float a2x = v[3], a2y = v[4], a2z = v[5];

    float n1 = a1x * a1x + a1y * a1y + a1z * a1z;
    float i1 = rsqrtf(fmaxf(n1, 1e-24f));
    float b1x = a1x * i1, b1y = a1y * i1, b1z = a1z * i1;

    float d = b1x * a2x + b1y * a2y + b1z * a2z;
    float ux = a2x - d * b1x;
    float uy = a2y - d * b1y;
    float uz = a2z - d * b1z;
    float n2 = ux * ux + uy * uy + uz * uz;
    float i2 = rsqrtf(fmaxf(n2, 1e-24f));
    float b2x = ux * i2, b2y = uy * i2, b2z = uz * i2;

    float b3x = b1y * b2z - b1z * b2y;
    float b3y = b1z * b2x - b1x * b2z;
    float b3z = b1x * b2y - b1y * b2x;

    L[0] = b1x; L[1] = b2x; L[2] = b3x;
    L[3] = b1y; L[4] = b2y; L[5] = b3y;
    L[6] = b1z; L[7] = b2z; L[8] = b3z;
}

// DFS over the binary-heap skeleton. j = joint index, d = depth (stack slot).
// gR[d-1] / ppos[d-1] hold the parent's global rotation / position.
template <int j, int d>
__device__ __forceinline__ void fk_node(const float* __restrict__ r6,
                                        float* __restrict__ o,
                                        float (&gR)[6][9],
                                        float (&ppos)[6][3],
                                        const float* __restrict__ rest) {
    float L[9];
    rot6d_to_mat(r6 + j * 6, L);

    // rest offset (warp-uniform -> L1 broadcast)
    float rx = __ldg(rest + j * 3 + 0);
    float ry = __ldg(rest + j * 3 + 1);
    float rz = __ldg(rest + j * 3 + 2);

    // local_rotated = L @ rest[j]
    float lr0 = L[0] * rx + L[1] * ry + L[2] * rz;
    float lr1 = L[3] * rx + L[4] * ry + L[5] * rz;
    float lr2 = L[6] * rx + L[7] * ry + L[8] * rz;

    // pos[j] = pos[p] + gR[p] @ lr
    float px = ppos[d - 1][0] + gR[d - 1][0] * lr0 + gR[d - 1][1] * lr1 + gR[d - 1][2] * lr2;
    float py = ppos[d - 1][1] + gR[d - 1][3] * lr0 + gR[d - 1][4] * lr1 + gR[d - 1][5] * lr2;
    float pz = ppos[d - 1][2] + gR[d - 1][6] * lr0 + gR[d - 1][7] * lr1 + gR[d - 1][8] * lr2;

    o[j * 3 + 0] = px;
    o[j * 3 + 1] = py;
    o[j * 3 + 2] = pz;

    if constexpr (2 * j + 1 < J_DIM) {
        // non-leaf: need gR[j] = gR[p] @ L
        ppos[d][0] = px; ppos[d][1] = py; ppos[d][2] = pz;
        #pragma unroll
        for (int i = 0; i < 3; i++) {
            float p0 = gR[d - 1][i * 3 + 0];
            float p1 = gR[d - 1][i * 3 + 1];
            float p2 = gR[d - 1][i * 3 + 2];
            gR[d][i * 3 + 0] = p0 * L[0] + p1 * L[3] + p2 * L[6];
            gR[d][i * 3 + 1] = p0 * L[1] + p1 * L[4] + p2 * L[7];
            gR[d][i * 3 + 2] = p0 * L[2] + p1 * L[5] + p2 * L[8];
        }
        fk_node<2 * j + 1, d + 1>(r6, o, gR, ppos, rest);
        if constexpr (2 * j + 2 < J_DIM) {
            fk_node<2 * j + 2, d + 1>(r6, o, gR, ppos, rest);
        }
    }
}

__global__ void __launch_bounds__(128)
fk_kernel(const float* __restrict__ rot6d,
          const float* __restrict__ trans,
          const float* __restrict__ yaw,
          const float* __restrict__ rest,
          float* __restrict__ out) {
    int bt = blockIdx.x * blockDim.x + threadIdx.x;
    if (bt >= NBT) return;

    const float* r6 = rot6d + (size_t)bt * J_DIM * 6;
    float* o = out + (size_t)bt * J_DIM * 3;

    float gR[6][9];
    float ppos[6][3];

    // Root: gR[0] = R_yaw @ local_R[0]; pos[0] = root_translation
    float L[9];
    rot6d_to_mat(r6, L);
    float sy, cy;
    __sincosf(yaw[bt], &sy, &cy);

    // R_yaw rows: [cy,0,sy], [0,1,0], [-sy,0,cy]
    gR[0][0] = cy * L[0] + sy * L[6];
    gR[0][1] = cy * L[1] + sy * L[7];
    gR[0][2] = cy * L[2] + sy * L[8];
    gR[0][3] = L[3];
    gR[0][4] = L[4];
    gR[0][5] = L[5];
    gR[0][6] = cy * L[6] - sy * L[0];
    gR[0][7] = cy * L[7] - sy * L[1];
    gR[0][8] = cy * L[8] - sy * L[2];

    float tx = trans[bt * 3 + 0];
    float ty = trans[bt * 3 + 1];
    float tz = trans[bt * 3 + 2];
    ppos[0][0] = tx; ppos[0][1] = ty; ppos[0][2] = tz;
    o[0] = tx; o[1] = ty; o[2] = tz;

    fk_node<1, 1>(r6, o, gR, ppos, rest);
    fk_node<2, 1>(r6, o, gR, ppos, rest);
}

extern "C" void kernel_launch(void* const* d_in, const int* in_sizes, int n_in,
                              void* d_out, int out_size) {
    const float* rot6d = (const float*)d_in[0];
    const float* trans = (const float*)d_in[1];
    const float* yaw   = (const float*)d_in[2];
    // d_in[3] = parents (int64) — tree is fixed at compile time, unused.
    const float* rest  = (const float*)d_in[4];
    float* out = (float*)d_out;

    dim3 block(128);
    dim3 grid((NBT + block.x - 1) / block.x);
    fk_kernel<<<grid, block>>>(rot6d, trans, yaw, rest, out);
}

// round 7
// speedup vs baseline: 1.9791x; 1.9791x over previous
#include <cuda_runtime.h>
#include <cuda_bf16.h>

#define B_DIM 32
#define T_DIM 1024
#define J_DIM 52
#define NBT (B_DIM * T_DIM)
#define SPLIT 8   // threads per (b,t): one per depth-3 subtree root (nodes 7..14)

// rot6d -> 3x3 rotation matrix (row-major, columns = b1,b2,b3).
// Records are 24 bytes, 8-byte aligned -> three float2 loads.
__device__ __forceinline__ void rot6d_to_mat_j(const float* __restrict__ r6, int j, float L[9]) {
    const float2* v = reinterpret_cast<const float2*>(r6 + j * 6);
    float2 q0 = v[0], q1 = v[1], q2 = v[2];
    float a1x = q0.x, a1y = q0.y, a1z = q1.x;
    float a2x = q1.y, a2y = q2.x, a2z = q2.y;

    float n1 = a1x * a1x + a1y * a1y + a1z * a1z;
    float i1 = rsqrtf(fmaxf(n1, 1e-24f));
    float b1x = a1x * i1, b1y = a1y * i1, b1z = a1z * i1;

    float d = b1x * a2x + b1y * a2y + b1z * a2z;
    float ux = a2x - d * b1x;
    float uy = a2y - d * b1y;
    float uz = a2z - d * b1z;
    float n2 = ux * ux + uy * uy + uz * uz;
    float i2 = rsqrtf(fmaxf(n2, 1e-24f));
    float b2x = ux * i2, b2y = uy * i2, b2z = uz * i2;

    float b3x = b1y * b2z - b1z * b2y;
    float b3y = b1z * b2x - b1x * b2z;
    float b3z = b1x * b2y - b1y * b2x;

    L[0] = b1x; L[1] = b2x; L[2] = b3x;
    L[3] = b1y; L[4] = b2y; L[5] = b3y;
    L[6] = b1z; L[7] = b2z; L[8] = b3z;
}

// One chain step at compile-time depth d (runtime joint j).
// Computes pos[j] from parent state in slot d-1; optionally fills slot d
// with (gR[j], pos[j]) for children.
template <int d>
__device__ __forceinline__ void chain_node(int j,
                                           const float* __restrict__ r6,
                                           const float* __restrict__ rest,
                                           float (&gR)[6][9], float (&ppos)[6][3],
                                           float& px, float& py, float& pz,
                                           bool make_gR) {
    float L[9];
    rot6d_to_mat_j(r6, j, L);

    float rx = __ldg(rest + j * 3 + 0);
    float ry = __ldg(rest + j * 3 + 1);
    float rz = __ldg(rest + j * 3 + 2);

    float lr0 = L[0] * rx + L[1] * ry + L[2] * rz;
    float lr1 = L[3] * rx + L[4] * ry + L[5] * rz;
    float lr2 = L[6] * rx + L[7] * ry + L[8] * rz;

    px = ppos[d - 1][0] + gR[d - 1][0] * lr0 + gR[d - 1][1] * lr1 + gR[d - 1][2] * lr2;
    py = ppos[d - 1][1] + gR[d - 1][3] * lr0 + gR[d - 1][4] * lr1 + gR[d - 1][5] * lr2;
    pz = ppos[d - 1][2] + gR[d - 1][6] * lr0 + gR[d - 1][7] * lr1 + gR[d - 1][8] * lr2;

    if (make_gR) {
        ppos[d][0] = px; ppos[d][1] = py; ppos[d][2] = pz;
        #pragma unroll
        for (int i = 0; i < 3; i++) {
            float p0 = gR[d - 1][i * 3 + 0];
            float p1 = gR[d - 1][i * 3 + 1];
            float p2 = gR[d - 1][i * 3 + 2];
            gR[d][i * 3 + 0] = p0 * L[0] + p1 * L[3] + p2 * L[6];
            gR[d][i * 3 + 1] = p0 * L[1] + p1 * L[4] + p2 * L[7];
            gR[d][i * 3 + 2] = p0 * L[2] + p1 * L[5] + p2 * L[8];
        }
    }
}

// DFS over a subtree; runtime joint index, compile-time depth (register stack slot).
template <int d>
__device__ __forceinline__ void fk_rec(int j,
                                       const float* __restrict__ r6,
                                       float* __restrict__ o,
                                       const float* __restrict__ rest,
                                       float (&gR)[6][9], float (&ppos)[6][3]) {
    float px, py, pz;
    bool has_child = (2 * j + 1 < J_DIM);
    chain_node<d>(j, r6, rest, gR, ppos, px, py, pz, has_child);

    o[j * 3 + 0] = px;
    o[j * 3 + 1] = py;
    o[j * 3 + 2] = pz;

    if constexpr (d < 5) {
        if (has_child) {
            fk_rec<d + 1>(2 * j + 1, r6, o, rest, gR, ppos);
            if (2 * j + 2 < J_DIM)
                fk_rec<d + 1>(2 * j + 2, r6, o, rest, gR, ppos);
        }
    }
}

__global__ void __launch_bounds__(256)
fk_kernel(const float* __restrict__ rot6d,
          const float* __restrict__ trans,
          const float* __restrict__ yaw,
          const float* __restrict__ rest,
          float* __restrict__ out) {
    int gid = blockIdx.x * blockDim.x + threadIdx.x;
    if (gid >= NBT * SPLIT) return;

    int bt = gid >> 3;        // (b,t) index
    int s  = gid & 7;         // subtree slot: handles subtree rooted at 7+s

    const float* r6 = rot6d + (size_t)bt * J_DIM * 6;
    float* o = out + (size_t)bt * J_DIM * 3;

    float gR[6][9];
    float ppos[6][3];

    // ---- root (node 0): gR[0] = R_yaw @ L0, pos = root_translation ----
    float L[9];
    rot6d_to_mat_j(r6, 0, L);
    float sy, cy;
    __sincosf(yaw[bt], &sy, &cy);

    gR[0][0] = cy * L[0] + sy * L[6];
    gR[0][1] = cy * L[1] + sy * L[7];
    gR[0][2] = cy * L[2] + sy * L[8];
    gR[0][3] = L[3];
    gR[0][4] = L[4];
    gR[0][5] = L[5];
    gR[0][6] = cy * L[6] - sy * L[0];
    gR[0][7] = cy * L[7] - sy * L[1];
    gR[0][8] = cy * L[8] - sy * L[2];

    float tx = trans[bt * 3 + 0];
    float ty = trans[bt * 3 + 1];
    float tz = trans[bt * 3 + 2];
    ppos[0][0] = tx; ppos[0][1] = ty; ppos[0][2] = tz;
    if (s == 0) { o[0] = tx; o[1] = ty; o[2] = tz; }

    // ---- path node at depth 1: n1 = 1 + (s>>2) ----
    {
        int n1 = 1 + (s >> 2);
        float px, py, pz;
        chain_node<1>(n1, r6, rest, gR, ppos, px, py, pz, true);
        if ((s & 3) == 0) {
            o[n1 * 3 + 0] = px;
            o[n1 * 3 + 1] = py;
            o[n1 * 3 + 2] = pz;
        }
    }

    // ---- path node at depth 2: n2 = 3 + (s>>1) ----
    {
        int n2 = 3 + (s >> 1);
        float px, py, pz;
        chain_node<2>(n2, r6, rest, gR, ppos, px, py, pz, true);
        if ((s & 1) == 0) {
            o[n2 * 3 + 0] = px;
            o[n2 * 3 + 1] = py;
            o[n2 * 3 + 2] = pz;
        }
    }

    // ---- own subtree rooted at 7+s (depth 3..5) ----
    fk_rec<3>(7 + s, r6, o, rest, gR, ppos);
}

extern "C" void kernel_launch(void* const* d_in, const int* in_sizes, int n_in,
                              void* d_out, int out_size) {
    const float* rot6d = (const float*)d_in[0];
    const float* trans = (const float*)d_in[1];
    const float* yaw   = (const float*)d_in[2];
    // d_in[3] = parents (int64) — binary-heap tree is fixed at compile time.
    const float* rest  = (const float*)d_in[4];
    float* out = (float*)d_out;

    int total = NBT * SPLIT;
    dim3 block(256);
    dim3 grid((total + block.x - 1) / block.x);
    fk_kernel<<<grid, block>>>(rot6d, trans, yaw, rest, out);
}

// round 8
// speedup vs baseline: 2.7631x; 1.3961x over previous
#include <cuda_runtime.h>
#include <cuda_bf16.h>

#define B_DIM 32
#define T_DIM 1024
#define J_DIM 52
#define NBT (B_DIM * T_DIM)
#define SPLIT 8            // threads per (b,t): one per depth-3 subtree root (nodes 7..14)
#define BT_PER_BLK 16      // (b,t) rows per block
#define THREADS (BT_PER_BLK * SPLIT)   // 128
#define IN_FLOATS (J_DIM * 6)          // 312 floats per bt
#define OUT_FLOATS (J_DIM * 3)         // 156 floats per bt

// rot6d -> 3x3 rotation matrix (row-major, columns = b1,b2,b3), reading from smem.
__device__ __forceinline__ void rot6d_to_mat_s(const float* __restrict__ r6, int j, float L[9]) {
    const float2* v = reinterpret_cast<const float2*>(r6 + j * 6);  // 8B-aligned (j*6 even)
    float2 q0 = v[0], q1 = v[1], q2 = v[2];
    float a1x = q0.x, a1y = q0.y, a1z = q1.x;
    float a2x = q1.y, a2y = q2.x, a2z = q2.y;

    float n1 = a1x * a1x + a1y * a1y + a1z * a1z;
    float i1 = rsqrtf(fmaxf(n1, 1e-24f));
    float b1x = a1x * i1, b1y = a1y * i1, b1z = a1z * i1;

    float d = b1x * a2x + b1y * a2y + b1z * a2z;
    float ux = a2x - d * b1x;
    float uy = a2y - d * b1y;
    float uz = a2z - d * b1z;
    float n2 = ux * ux + uy * uy + uz * uz;
    float i2 = rsqrtf(fmaxf(n2, 1e-24f));
    float b2x = ux * i2, b2y = uy * i2, b2z = uz * i2;

    float b3x = b1y * b2z - b1z * b2y;
    float b3y = b1z * b2x - b1x * b2z;
    float b3z = b1x * b2y - b1y * b2x;

    L[0] = b1x; L[1] = b2x; L[2] = b3x;
    L[3] = b1y; L[4] = b2y; L[5] = b3y;
    L[6] = b1z; L[7] = b2z; L[8] = b3z;
}

// One chain step at compile-time depth d (runtime joint j).
template <int d>
__device__ __forceinline__ void chain_node(int j,
                                           const float* __restrict__ r6,
                                           const float* __restrict__ rest,
                                           float (&gR)[6][9], float (&ppos)[6][3],
                                           float& px, float& py, float& pz,
                                           bool make_gR) {
    float L[9];
    rot6d_to_mat_s(r6, j, L);

    float rx = __ldg(rest + j * 3 + 0);
    float ry = __ldg(rest + j * 3 + 1);
    float rz = __ldg(rest + j * 3 + 2);

    float lr0 = L[0] * rx + L[1] * ry + L[2] * rz;
    float lr1 = L[3] * rx + L[4] * ry + L[5] * rz;
    float lr2 = L[6] * rx + L[7] * ry + L[8] * rz;

    px = ppos[d - 1][0] + gR[d - 1][0] * lr0 + gR[d - 1][1] * lr1 + gR[d - 1][2] * lr2;
    py = ppos[d - 1][1] + gR[d - 1][3] * lr0 + gR[d - 1][4] * lr1 + gR[d - 1][5] * lr2;
    pz = ppos[d - 1][2] + gR[d - 1][6] * lr0 + gR[d - 1][7] * lr1 + gR[d - 1][8] * lr2;

    if (make_gR) {
        ppos[d][0] = px; ppos[d][1] = py; ppos[d][2] = pz;
        #pragma unroll
        for (int i = 0; i < 3; i++) {
            float p0 = gR[d - 1][i * 3 + 0];
            float p1 = gR[d - 1][i * 3 + 1];
            float p2 = gR[d - 1][i * 3 + 2];
            gR[d][i * 3 + 0] = p0 * L[0] + p1 * L[3] + p2 * L[6];
            gR[d][i * 3 + 1] = p0 * L[1] + p1 * L[4] + p2 * L[7];
            gR[d][i * 3 + 2] = p0 * L[2] + p1 * L[5] + p2 * L[8];
        }
    }
}

// DFS over a subtree; runtime joint index, compile-time depth (register stack slot).
template <int d>
__device__ __forceinline__ void fk_rec(int j,
                                       const float* __restrict__ r6,
                                       float* __restrict__ o,
                                       const float* __restrict__ rest,
                                       float (&gR)[6][9], float (&ppos)[6][3]) {
    float px, py, pz;
    bool has_child = (2 * j + 1 < J_DIM);
    chain_node<d>(j, r6, rest, gR, ppos, px, py, pz, has_child);

    o[j * 3 + 0] = px;
    o[j * 3 + 1] = py;
    o[j * 3 + 2] = pz;

    if constexpr (d < 5) {
        if (has_child) {
            fk_rec<d + 1>(2 * j + 1, r6, o, rest, gR, ppos);
            if (2 * j + 2 < J_DIM)
                fk_rec<d + 1>(2 * j + 2, r6, o, rest, gR, ppos);
        }
    }
}

__global__ void __launch_bounds__(THREADS)
fk_kernel(const float* __restrict__ rot6d,
          const float* __restrict__ trans,
          const float* __restrict__ yaw,
          const float* __restrict__ rest,
          float* __restrict__ out) {
    __shared__ float s_in[BT_PER_BLK * IN_FLOATS];    // 16*312*4 = 19968 B
    __shared__ float s_out[BT_PER_BLK * OUT_FLOATS];  // 16*156*4 =  9984 B

    int tid = threadIdx.x;
    int blk = blockIdx.x;

    // ---- Phase 1: coalesced float4 load of 16 rot6d rows into smem ----
    {
        const float4* gsrc = reinterpret_cast<const float4*>(
            rot6d + (size_t)blk * BT_PER_BLK * IN_FLOATS);
        float4* sdst = reinterpret_cast<float4*>(s_in);
        const int n4 = BT_PER_BLK * IN_FLOATS / 4;   // 1248
        #pragma unroll
        for (int i = tid; i < n4; i += THREADS)
            sdst[i] = gsrc[i];
    }
    __syncthreads();

    // ---- Phase 2: compute (8 threads per bt, subtree split) ----
    {
        int bt_local = tid >> 3;
        int s = tid & 7;
        int bt = blk * BT_PER_BLK + bt_local;

        const float* r6 = s_in + bt_local * IN_FLOATS;
        float* o = s_out + bt_local * OUT_FLOATS;

        float gR[6][9];
        float ppos[6][3];

        // root (node 0): gR[0] = R_yaw @ L0, pos = root_translation
        float L[9];
        rot6d_to_mat_s(r6, 0, L);
        float sy, cy;
        __sincosf(yaw[bt], &sy, &cy);

        gR[0][0] = cy * L[0] + sy * L[6];
        gR[0][1] = cy * L[1] + sy * L[7];
        gR[0][2] = cy * L[2] + sy * L[8];
        gR[0][3] = L[3];
        gR[0][4] = L[4];
        gR[0][5] = L[5];
        gR[0][6] = cy * L[6] - sy * L[0];
        gR[0][7] = cy * L[7] - sy * L[1];
        gR[0][8] = cy * L[8] - sy * L[2];

        float tx = trans[bt * 3 + 0];
        float ty = trans[bt * 3 + 1];
        float tz = trans[bt * 3 + 2];
        ppos[0][0] = tx; ppos[0][1] = ty; ppos[0][2] = tz;
        if (s == 0) { o[0] = tx; o[1] = ty; o[2] = tz; }

        // path node at depth 1: n1 = 1 + (s>>2)
        {
            int n1 = 1 + (s >> 2);
            float px, py, pz;
            chain_node<1>(n1, r6, rest, gR, ppos, px, py, pz, true);
            if ((s & 3) == 0) {
                o[n1 * 3 + 0] = px; o[n1 * 3 + 1] = py; o[n1 * 3 + 2] = pz;
            }
        }

        // path node at depth 2: n2 = 3 + (s>>1)
        {
            int n2 = 3 + (s >> 1);
            float px, py, pz;
            chain_node<2>(n2, r6, rest, gR, ppos, px, py, pz, true);
            if ((s & 1) == 0) {
                o[n2 * 3 + 0] = px; o[n2 * 3 + 1] = py; o[n2 * 3 + 2] = pz;
            }
        }

        // own subtree rooted at 7+s (depth 3..5)
        fk_rec<3>(7 + s, r6, o, rest, gR, ppos);
    }
    __syncthreads();

    // ---- Phase 3: coalesced float4 store of 16 output rows ----
    {
        float4* gdst = reinterpret_cast<float4*>(
            out + (size_t)blk * BT_PER_BLK * OUT_FLOATS);
        const float4* ssrc = reinterpret_cast<const float4*>(s_out);
        const int n4 = BT_PER_BLK * OUT_FLOATS / 4;  // 624
        #pragma unroll
        for (int i = tid; i < n4; i += THREADS)
            gdst[i] = ssrc[i];
    }
}

extern "C" void kernel_launch(void* const* d_in, const int* in_sizes, int n_in,
                              void* d_out, int out_size) {
    const float* rot6d = (const float*)d_in[0];
    const float* trans = (const float*)d_in[1];
    const float* yaw   = (const float*)d_in[2];
    // d_in[3] = parents (int64) — binary-heap tree is fixed at compile time.
    const float* rest  = (const float*)d_in[4];
    float* out = (float*)d_out;

    dim3 block(THREADS);
    dim3 grid(NBT / BT_PER_BLK);   // 2048 blocks, exact
    fk_kernel<<<grid, block>>>(rot6d, trans, yaw, rest, out);
}